// round 11
// baseline (speedup 1.0000x reference)
#include <cuda_runtime.h>
#include <cuda_bf16.h>
#include <cuda_fp16.h>
#include <math_constants.h>
#include <cstdint>

#define B 4
#define C 256
#define NPTS 4096
#define KNN 5
#define C2 512
#define KHW 512   // d_xs halfwords per point row (hi 256 | lo 256)
#define NC 12     // approx candidates kept per point

// ---------------- scratch (device globals: no allocation allowed) ----------
__device__ float d_xx[B*NPTS];                       // 0.5 * ||x_n||^2
__device__ __half d_vu[B*NPTS*C2];                   // v|u features, fp16
__device__ int   d_idx[B*NPTS*KNN];
__device__ int   d_cand[B*NPTS*NC];                  // top-12 approx candidates
__device__ float d_psum [256*C];
__device__ float d_psum2[256*C];
__device__ float d_scale[C];
__device__ float d_shift[C];
__device__ __align__(16) uint16_t d_xs[B*NPTS*KHW];  // [b][n][k] bf16 hi|lo
__device__ __align__(16) float d_xt[B*NPTS*C];       // [b][n][c] fp32 row-major
__device__ __align__(16) uint16_t d_Ws[C2*768];      // [j][k] bf16: Whi|Whi|Wlo

// ---------------- baseline-PTX helpers (NO tcgen05 anywhere) ---------------
__device__ __forceinline__ uint32_t smem_u32(const void* p) {
    uint32_t a;
    asm("{ .reg .u64 t; cvta.to.shared.u64 t, %1; cvt.u32.u64 %0, t; }" : "=r"(a) : "l"(p));
    return a;
}
__device__ __forceinline__ void cp16(uint32_t dst, const void* src) {
    asm volatile("cp.async.cg.shared.global [%0], [%1], 16;" :: "r"(dst), "l"(src) : "memory");
}
#define CP_COMMIT() asm volatile("cp.async.commit_group;" ::: "memory")
#define CP_WAIT1()  asm volatile("cp.async.wait_group 1;" ::: "memory")

__device__ __forceinline__ void ldsm4(uint32_t& r0, uint32_t& r1, uint32_t& r2, uint32_t& r3,
                                      uint32_t addr) {
    asm volatile("ldmatrix.sync.aligned.m8n8.x4.shared.b16 {%0,%1,%2,%3}, [%4];"
                 : "=r"(r0), "=r"(r1), "=r"(r2), "=r"(r3) : "r"(addr));
}
__device__ __forceinline__ void mma16816(float* c,
                                         const uint32_t* a, uint32_t b0, uint32_t b1) {
    asm volatile("mma.sync.aligned.m16n8k16.row.col.f32.bf16.bf16.f32 "
                 "{%0,%1,%2,%3}, {%4,%5,%6,%7}, {%8,%9}, {%0,%1,%2,%3};"
                 : "+f"(c[0]), "+f"(c[1]), "+f"(c[2]), "+f"(c[3])
                 : "r"(a[0]), "r"(a[1]), "r"(a[2]), "r"(a[3]), "r"(b0), "r"(b1));
}

#define INS5(tv, ti) do { if (v > tv[4]) { float _v = v; int _i = ii;                 \
    _Pragma("unroll") for (int _q = 0; _q < 5; _q++) {                                \
        bool g = _v > tv[_q]; float ov = tv[_q]; int oi = ti[_q];                     \
        tv[_q] = g ? _v : ov; ti[_q] = g ? _i : oi;                                   \
        _v = g ? ov : _v; _i = g ? oi : _i; } } } while(0)

// ---------------- prep: xx = 0.5 * sum_c x^2 -------------------------------
__global__ void prep_xx(const float* __restrict__ x) {
    int b = blockIdx.y;
    int n = blockIdx.x*256 + threadIdx.x;
    const float* xb = x + b*C*NPTS + n;
    float s = 0.f;
    #pragma unroll 8
    for (int c = 0; c < C; c++) { float v = xb[c*NPTS]; s = fmaf(v, v, s); }
    d_xx[b*NPTS + n] = 0.5f * s;
}

// --------- prep: stacked bf16 weights Ws[j][k] = Whi | Whi | Wlo -----------
__global__ void prep_wbf(const float* __restrict__ W) {
    int e = blockIdx.x*256 + threadIdx.x;       // e < 512*256
    int j = e >> 8, c = e & 255;
    float w;
    if (j < 256) w = W[j*C2 + c];
    else { int o = j - 256; w = W[o*C2 + 256 + c] - W[o*C2 + c]; }
    __nv_bfloat16 hi = __float2bfloat16(w);
    __nv_bfloat16 lo = __float2bfloat16(w - __bfloat162float(hi));
    uint16_t hb = __bfloat16_as_ushort(hi), lb = __bfloat16_as_ushort(lo);
    d_Ws[(size_t)j*768 + c]       = hb;
    d_Ws[(size_t)j*768 + 256 + c] = hb;
    d_Ws[(size_t)j*768 + 512 + c] = lb;
}

// ------- prep: bf16 hi/lo split + fp32 transpose, both to [b][n][.] --------
__global__ void __launch_bounds__(256) prep_split(const float* __restrict__ x) {
    __shared__ float tile[64][65];
    int b = blockIdx.z, c0 = blockIdx.y*64, n0 = blockIdx.x*64;
    int tid = threadIdx.x;
    #pragma unroll
    for (int i = 0; i < 16; i++) {
        int e = tid + 256*i;
        int cl = e >> 6, nl = e & 63;
        tile[cl][nl] = x[(b*C + c0 + cl)*NPTS + n0 + nl];
    }
    __syncthreads();
    int nl = tid >> 2, cq = (tid & 3) * 16;
    uint16_t* oh = d_xs + ((size_t)(b*NPTS + n0 + nl))*KHW + c0 + cq;
    uint16_t* ol = oh + 256;
    float*    ot = d_xt + ((size_t)(b*NPTS + n0 + nl))*C + c0 + cq;
    #pragma unroll
    for (int j = 0; j < 16; j += 2) {
        float v0 = tile[cq+j][nl],  v1 = tile[cq+j+1][nl];
        __nv_bfloat16 h0 = __float2bfloat16(v0), h1 = __float2bfloat16(v1);
        __nv_bfloat16 l0 = __float2bfloat16(v0 - __bfloat162float(h0));
        __nv_bfloat16 l1 = __float2bfloat16(v1 - __bfloat162float(h1));
        *(uint32_t*)(oh + j) = (uint32_t)__bfloat16_as_ushort(h0) | ((uint32_t)__bfloat16_as_ushort(h1) << 16);
        *(uint32_t*)(ol + j) = (uint32_t)__bfloat16_as_ushort(l0) | ((uint32_t)__bfloat16_as_ushort(l1) << 16);
        *(float2*)(ot + j) = make_float2(v0, v1);
    }
}

// ---- KNN via bf16 HMMA, K=256, 16 warps, warp tile 32x32 (4x4 warps) ------
// grid (32, B), 512 threads. A: 128 rows x 256hw resident (stride 528B).
// B: 128-row full-K chunks, double-buffered. Rank = <n,m> - 0.5||m||^2.
// Warp = rowgroup rg (32 rows) x colgroup cg (32 cols): B dup 4x, A dup 4x.
#define SMA   0                      // 128*528 = 67584
#define SMB   67584                  // 2 * 67584
#define SMBUF 67584
#define SMXX  202752                 // 16384
#define SMTOT 219136
#define SMCV  SMB                    // merge buffers alias B (128*80*4 = 40960)
#define SMCI  (SMB + 40960)

__global__ void __launch_bounds__(512, 1) knn_mma() {
    extern __shared__ __align__(16) char smem[];
    uint32_t sb = smem_u32(smem);
    int b = blockIdx.y, n0 = blockIdx.x * 128;
    int tid = threadIdx.x, lane = tid & 31, wid = tid >> 5;
    int rg = wid >> 2, cg = wid & 3;
    const uint16_t* xsb = d_xs + (size_t)b*NPTS*KHW;

    // group0: A (hi 256 hw) + xx + B chunk 0
    #pragma unroll
    for (int i = 0; i < 8; i++) {
        int c = tid + 512*i; int row = c >> 5, col = c & 31;
        cp16(sb + SMA + row*528 + col*16, xsb + (size_t)(n0+row)*KHW + col*8);
    }
    #pragma unroll
    for (int i = 0; i < 2; i++) {
        int c = tid + 512*i;
        cp16(sb + SMXX + c*16, d_xx + b*NPTS + c*4);
    }
    #pragma unroll
    for (int i = 0; i < 8; i++) {
        int c = tid + 512*i; int row = c >> 5, col = c & 31;
        cp16(sb + SMB + row*528 + col*16, xsb + (size_t)row*KHW + col*8);
    }
    CP_COMMIT();
    // group1: B chunk 1
    #pragma unroll
    for (int i = 0; i < 8; i++) {
        int c = tid + 512*i; int row = c >> 5, col = c & 31;
        cp16(sb + SMB + SMBUF + row*528 + col*16, xsb + (size_t)(128+row)*KHW + col*8);
    }
    CP_COMMIT();

    float tv[4][5]; int tix[4][5];
    #pragma unroll
    for (int L = 0; L < 4; L++)
        #pragma unroll
        for (int j = 0; j < 5; j++) { tv[L][j] = -CUDART_INF_F; tix[L][j] = 0; }
    const float* xx_s = (const float*)(smem + SMXX);

    int q = lane >> 3, l7 = lane & 7;
    // A mapping: (q&1) rows, (q>>1) k-bytes.  B mapping (verified R5/R10): swapped.
    uint32_t arow0 = (uint32_t)((rg*32 + (q & 1)*8 + l7)*528 + (q >> 1)*16);
    uint32_t arow1 = arow0 + 16*528;
    uint32_t brow0 = (uint32_t)((cg*32 + (q >> 1)*8 + l7)*528 + (q & 1)*16);
    uint32_t brow1 = brow0 + 16*528;

    for (int mt = 0; mt < 32; mt++) {
        CP_WAIT1();
        __syncthreads();
        float acc[2][4][4];
        #pragma unroll
        for (int a = 0; a < 2; a++)
            #pragma unroll
            for (int p = 0; p < 4; p++)
                #pragma unroll
                for (int j = 0; j < 4; j++) acc[a][p][j] = 0.f;

        uint32_t ba = sb + SMA;
        uint32_t bb = sb + SMB + (mt & 1)*SMBUF;
        #pragma unroll
        for (int ks = 0; ks < 16; ks++) {
            uint32_t a0[4], a1[4], b0[4], b1[4];
            ldsm4(a0[0], a0[1], a0[2], a0[3], ba + arow0 + ks*32);
            ldsm4(a1[0], a1[1], a1[2], a1[3], ba + arow1 + ks*32);
            ldsm4(b0[0], b0[1], b0[2], b0[3], bb + brow0 + ks*32);
            ldsm4(b1[0], b1[1], b1[2], b1[3], bb + brow1 + ks*32);
            mma16816(acc[0][0], a0, b0[0], b0[1]);
            mma16816(acc[0][1], a0, b0[2], b0[3]);
            mma16816(acc[0][2], a0, b1[0], b1[1]);
            mma16816(acc[0][3], a0, b1[2], b1[3]);
            mma16816(acc[1][0], a1, b0[0], b0[1]);
            mma16816(acc[1][1], a1, b0[2], b0[3]);
            mma16816(acc[1][2], a1, b1[0], b1[1]);
            mma16816(acc[1][3], a1, b1[2], b1[3]);
        }
        // epilogue: rank value <n,m> - 0.5||m||^2, streaming top-5
        int m0 = mt * 128;
        #pragma unroll
        for (int a = 0; a < 2; a++) {
            #pragma unroll
            for (int p = 0; p < 4; p++) {
                int cb = m0 + cg*32 + p*8 + 2*(lane & 3);
                float xm0 = xx_s[cb], xm1 = xx_s[cb + 1];
                float v; int ii;
                v = acc[a][p][0] - xm0; ii = cb;     INS5(tv[2*a],   tix[2*a]);
                v = acc[a][p][1] - xm1; ii = cb + 1; INS5(tv[2*a],   tix[2*a]);
                v = acc[a][p][2] - xm0; ii = cb;     INS5(tv[2*a+1], tix[2*a+1]);
                v = acc[a][p][3] - xm1; ii = cb + 1; INS5(tv[2*a+1], tix[2*a+1]);
            }
        }
        __syncthreads();   // all warps done reading buffer mt&1
        if (mt + 2 < 32) {
            int nm = mt + 2;
            #pragma unroll
            for (int i = 0; i < 8; i++) {
                int c = tid + 512*i; int row = c >> 5, col = c & 31;
                cp16(sb + SMB + (mt & 1)*SMBUF + row*528 + col*16,
                     xsb + (size_t)(nm*128 + row)*KHW + col*8);
            }
        }
        CP_COMMIT();       // possibly-empty group keeps depth constant
    }

    // merge: per row, 4 cg warps x 4 lanes x 5 = 80 candidates -> top-12
    float* cv  = (float*)(smem + SMCV);
    int*   cix = (int*)  (smem + SMCI);
    int slot = (cg*4 + (lane & 3)) * 5;
    #pragma unroll
    for (int L = 0; L < 4; L++) {
        int r = rg*32 + (L >> 1)*16 + (L & 1)*8 + (lane >> 2);
        #pragma unroll
        for (int j = 0; j < 5; j++) {
            cv [r*80 + slot + j] = tv[L][j];
            cix[r*80 + slot + j] = tix[L][j];
        }
    }
    __syncthreads();
    if (tid < 128) {
        #pragma unroll
        for (int s = 0; s < NC; s++) {
            float best = -CUDART_INF_F; int bi = 0;
            for (int e = 0; e < 80; e++) {
                float v = cv[tid*80 + e];
                if (v > best) { best = v; bi = e; }
            }
            d_cand[(b*NPTS + n0 + tid)*NC + s] = cix[tid*80 + bi];
            cv[tid*80 + bi] = -CUDART_INF_F;
        }
    }
}

// -------- verify: exact fp32 re-rank of the 12 candidates, warp/point ------
// rank value = <q,m> - 0.5||m||^2
__global__ void __launch_bounds__(128) verify_kernel() {
    int gw   = (blockIdx.x*128 + threadIdx.x) >> 5;
    int lane = threadIdx.x & 31;
    int b = gw >> 12;
    const float* xq = d_xt + (size_t)gw*C;
    float4 q0 = ((const float4*)xq)[lane];
    float4 q1 = ((const float4*)xq)[lane + 32];
    float pw[NC]; int cid[NC];
    #pragma unroll
    for (int k = 0; k < NC; k++) {
        int m = d_cand[gw*NC + k];
        cid[k] = m;
        const float* xc = d_xt + ((size_t)(b*NPTS + m))*C;
        float4 c0 = ((const float4*)xc)[lane];
        float4 c1 = ((const float4*)xc)[lane + 32];
        float s = 0.f;
        s = fmaf(q0.x, c0.x, s); s = fmaf(q0.y, c0.y, s);
        s = fmaf(q0.z, c0.z, s); s = fmaf(q0.w, c0.w, s);
        s = fmaf(q1.x, c1.x, s); s = fmaf(q1.y, c1.y, s);
        s = fmaf(q1.z, c1.z, s); s = fmaf(q1.w, c1.w, s);
        #pragma unroll
        for (int o = 16; o > 0; o >>= 1) s += __shfl_xor_sync(0xFFFFFFFFu, s, o);
        pw[k] = s - d_xx[b*NPTS + m];
    }
    if (lane == 0) {
        #pragma unroll
        for (int s5 = 0; s5 < KNN; s5++) {
            float best = -CUDART_INF_F; int bi = 0;
            #pragma unroll
            for (int e = 0; e < NC; e++) if (pw[e] > best) { best = pw[e]; bi = e; }
            d_idx[gw*KNN + s5] = cid[bi];
            pw[bi] = -CUDART_INF_F;
        }
    }
}

// ------- vu = Ws @ x via HMMA 3-term split (K=768), fp16 out ---------------
#define VBUF 36864    // per buffer: As 128*144=18432 + Bs 18432
#define VSMT 73728

__global__ void __launch_bounds__(256) vu_mma() {
    extern __shared__ __align__(16) char smem[];
    uint32_t sb = smem_u32(smem);
    int b = blockIdx.z, m0 = blockIdx.x*128, j0 = blockIdx.y*128;
    int tid = threadIdx.x, lane = tid & 31, wid = tid >> 5;
    int ngrp = wid >> 1, mhalf = wid & 1;

    int q = lane >> 3, l7 = lane & 7;
    uint32_t aoff = (uint32_t)((ngrp*32 + (q & 1)*8 + l7) * 144 + (q >> 1) * 16);
    uint32_t boff = (uint32_t)(18432 + (mhalf*64 + (q >> 1)*8 + l7) * 144 + (q & 1) * 16);

    #pragma unroll
    for (int pc = 0; pc < 2; pc++) {
        int koff = pc * 64;
        #pragma unroll
        for (int i = 0; i < 4; i++) {
            int c = tid + 256*i; int row = c >> 3, col = c & 7;
            cp16(sb + pc*VBUF + row*144 + col*16,
                 d_xs + (size_t)(b*NPTS + m0 + row)*KHW + koff + col*8);
            cp16(sb + pc*VBUF + 18432 + row*144 + col*16,
                 d_Ws + (size_t)(j0 + row)*768 + pc*64 + col*8);
        }
        CP_COMMIT();
    }

    float acc[2][8][4];
    #pragma unroll
    for (int ra = 0; ra < 2; ra++)
        #pragma unroll
        for (int t = 0; t < 8; t++)
            #pragma unroll
            for (int j = 0; j < 4; j++) acc[ra][t][j] = 0.f;

    for (int kc = 0; kc < 12; kc++) {
        CP_WAIT1();
        __syncthreads();
        uint32_t ba = sb + (kc & 1)*VBUF;
        #pragma unroll
        for (int ks = 0; ks < 4; ks++) {
            uint32_t a0[4], a1[4];
            ldsm4(a0[0], a0[1], a0[2], a0[3], ba + aoff + ks*32);
            ldsm4(a1[0], a1[1], a1[2], a1[3], ba + aoff + 2304 + ks*32);
            #pragma unroll
            for (int p = 0; p < 4; p++) {
                uint32_t b0, b1, b2, b3;
                ldsm4(b0, b1, b2, b3, ba + boff + p*2304 + ks*32);
                mma16816(acc[0][2*p],   a0, b0, b1);
                mma16816(acc[0][2*p+1], a0, b2, b3);
                mma16816(acc[1][2*p],   a1, b0, b1);
                mma16816(acc[1][2*p+1], a1, b2, b3);
            }
        }
        __syncthreads();
        if (kc + 2 < 12) {
            int nc2 = kc + 2;
            int koff = (nc2 < 8) ? nc2*64 : (nc2 - 8)*64;
            #pragma unroll
            for (int i = 0; i < 4; i++) {
                int c = tid + 256*i; int row = c >> 3, col = c & 7;
                cp16(sb + (kc & 1)*VBUF + row*144 + col*16,
                     d_xs + (size_t)(b*NPTS + m0 + row)*KHW + koff + col*8);
                cp16(sb + (kc & 1)*VBUF + 18432 + row*144 + col*16,
                     d_Ws + (size_t)(j0 + row)*768 + nc2*64 + col*8);
            }
        }
        CP_COMMIT();
    }

    #pragma unroll
    for (int ra = 0; ra < 2; ra++) {
        int r  = m0 + ngrp*32 + ra*16 + (lane >> 2);
        #pragma unroll
        for (int t = 0; t < 8; t++) {
            int cb = j0 + mhalf*64 + t*8 + 2*(lane & 3);
            __half2 h0 = __floats2half2_rn(acc[ra][t][0], acc[ra][t][1]);
            __half2 h1 = __floats2half2_rn(acc[ra][t][2], acc[ra][t][3]);
            *(__half2*)&d_vu[(size_t)(b*NPTS + r)*C2 + cb]     = h0;
            *(__half2*)&d_vu[(size_t)(b*NPTS + r + 8)*C2 + cb] = h1;
        }
    }
}

// ---------------- BN stats (fp16 vu) ---------------------------------------
__global__ void __launch_bounds__(256) stats_kernel() {
    int b  = blockIdx.y;
    int n0 = blockIdx.x * 64;
    int o  = threadIdx.x;
    float s = 0.f, s2 = 0.f;
    for (int nl = 0; nl < 64; nl++) {
        int n = n0 + nl;
        const __half* vun = d_vu + (size_t)(b*NPTS + n)*C2;
        float u = __half2float(vun[256 + o]);
        const int* ip = d_idx + (b*NPTS + n)*KNN;
        #pragma unroll
        for (int k = 0; k < KNN; k++) {
            int m = ip[k];
            float y = __half2float(d_vu[(size_t)(b*NPTS + m)*C2 + o]) + u;
            s += y;
            s2 = fmaf(y, y, s2);
        }
    }
    int pb = blockIdx.y*64 + blockIdx.x;
    d_psum [pb*C + o] = s;
    d_psum2[pb*C + o] = s2;
}

__global__ void bn_finalize(const float* __restrict__ gamma, const float* __restrict__ beta) {
    int o = threadIdx.x;
    float s = 0.f, s2 = 0.f;
    for (int pb = 0; pb < 256; pb++) { s += d_psum[pb*C + o]; s2 += d_psum2[pb*C + o]; }
    float cnt  = (float)(B*NPTS*KNN);
    float mean = s / cnt;
    float var  = s2 / cnt - mean*mean;
    float sc   = gamma[o] * rsqrtf(var + 1e-5f);
    d_scale[o] = sc;
    d_shift[o] = beta[o] - mean*sc;
}

// ---------------- final (fp16 vu) ------------------------------------------
__global__ void __launch_bounds__(256) final_kernel(const float* __restrict__ x,
                                                    float* __restrict__ out) {
    __shared__ float res[256][33];
    int b = blockIdx.y, n0 = blockIdx.x*32;
    int o = threadIdx.x;
    float sc = d_scale[o], sh = d_shift[o];
    for (int nl = 0; nl < 32; nl++) {
        int n = n0 + nl;
        const __half* vun = d_vu + (size_t)(b*NPTS + n)*C2;
        float u  = __half2float(vun[256 + o]);
        float cc = fmaf(u, sc, sh);
        const int* ip = d_idx + (b*NPTS + n)*KNN;
        float mx = -CUDART_INF_F;
        #pragma unroll
        for (int k = 0; k < KNN; k++) {
            float v = __half2float(d_vu[(size_t)(b*NPTS + ip[k])*C2 + o]);
            mx = fmaxf(mx, fmaf(v, sc, cc));
        }
        res[o][nl] = fmaxf(mx, 0.f);
    }
    __syncthreads();
    int lane = threadIdx.x & 31, og = threadIdx.x >> 5;
    #pragma unroll 4
    for (int p = 0; p < 32; p++) {
        int oo = p*8 + og;
        int gi = (b*C + oo)*NPTS + n0 + lane;
        out[gi] = res[oo][lane] + x[gi];
    }
}

// ---------------- launch ---------------------------------------------------
extern "C" void kernel_launch(void* const* d_in, const int* in_sizes, int n_in,
                              void* d_out, int out_size) {
    const float* x     = (const float*)d_in[0];
    const float* W     = (const float*)d_in[1];
    const float* gamma = (const float*)d_in[2];
    const float* beta  = (const float*)d_in[3];
    float* out = (float*)d_out;

    cudaFuncSetAttribute(knn_mma, cudaFuncAttributeMaxDynamicSharedMemorySize, SMTOT);
    cudaFuncSetAttribute(vu_mma,  cudaFuncAttributeMaxDynamicSharedMemorySize, VSMT);

    prep_xx      <<<dim3(NPTS/256, B), 256>>>(x);
    prep_wbf     <<<dim3(C2*C/256), 256>>>(W);
    prep_split   <<<dim3(NPTS/64, C/64, B), 256>>>(x);
    knn_mma      <<<dim3(NPTS/128, B), 512, SMTOT>>>();
    verify_kernel<<<dim3(B*NPTS/4), 128>>>();
    vu_mma       <<<dim3(NPTS/128, C2/128, B), 256, VSMT>>>();
    stats_kernel <<<dim3(NPTS/64, B), 256>>>();
    bn_finalize  <<<1, 256>>>(gamma, beta);
    final_kernel <<<dim3(NPTS/32, B), 256>>>(x, out);
}

// round 14
// speedup vs baseline: 1.0816x; 1.0816x over previous
#include <cuda_runtime.h>
#include <cuda_bf16.h>
#include <cuda_fp16.h>
#include <math_constants.h>
#include <cstdint>

#define B 4
#define C 256
#define NPTS 4096
#define KNN 5
#define C2 512
#define KHW 512   // d_xs halfwords per point row (hi 256 | lo 256)
#define NC 12     // approx candidates kept per point

// ---------------- scratch (device globals: no allocation allowed) ----------
__device__ float d_xx[B*NPTS];                       // 0.5 * ||x_n||^2
__device__ __half d_vu[B*NPTS*C2];                   // v|u features, fp16
__device__ int   d_idx[B*NPTS*KNN];
__device__ int   d_cand[B*NPTS*NC];                  // top-12 approx candidates
__device__ float d_psum [256*C];
__device__ float d_psum2[256*C];
__device__ float d_scale[C];
__device__ float d_shift[C];
__device__ __align__(16) uint16_t d_xs[B*NPTS*KHW];  // [b][n][k] bf16 hi|lo
__device__ __align__(16) float d_xt[B*NPTS*C];       // [b][n][c] fp32 (verify MUST be exact)
__device__ __align__(16) uint16_t d_Ws[C2*768];      // [j][k] bf16: Whi|Whi|Wlo

// ---------------- baseline-PTX helpers (NO tcgen05 anywhere) ---------------
__device__ __forceinline__ uint32_t smem_u32(const void* p) {
    uint32_t a;
    asm("{ .reg .u64 t; cvta.to.shared.u64 t, %1; cvt.u32.u64 %0, t; }" : "=r"(a) : "l"(p));
    return a;
}
__device__ __forceinline__ void cp16(uint32_t dst, const void* src) {
    asm volatile("cp.async.cg.shared.global [%0], [%1], 16;" :: "r"(dst), "l"(src) : "memory");
}
#define CP_COMMIT() asm volatile("cp.async.commit_group;" ::: "memory")
#define CP_WAIT1()  asm volatile("cp.async.wait_group 1;" ::: "memory")

__device__ __forceinline__ void ldsm4(uint32_t& r0, uint32_t& r1, uint32_t& r2, uint32_t& r3,
                                      uint32_t addr) {
    asm volatile("ldmatrix.sync.aligned.m8n8.x4.shared.b16 {%0,%1,%2,%3}, [%4];"
                 : "=r"(r0), "=r"(r1), "=r"(r2), "=r"(r3) : "r"(addr));
}
__device__ __forceinline__ void mma16816(float* c,
                                         const uint32_t* a, uint32_t b0, uint32_t b1) {
    asm volatile("mma.sync.aligned.m16n8k16.row.col.f32.bf16.bf16.f32 "
                 "{%0,%1,%2,%3}, {%4,%5,%6,%7}, {%8,%9}, {%0,%1,%2,%3};"
                 : "+f"(c[0]), "+f"(c[1]), "+f"(c[2]), "+f"(c[3])
                 : "r"(a[0]), "r"(a[1]), "r"(a[2]), "r"(a[3]), "r"(b0), "r"(b1));
}

#define INS5(tv, ti) do { if (v > tv[4]) { float _v = v; int _i = ii;                 \
    _Pragma("unroll") for (int _q = 0; _q < 5; _q++) {                                \
        bool g = _v > tv[_q]; float ov = tv[_q]; int oi = ti[_q];                     \
        tv[_q] = g ? _v : ov; ti[_q] = g ? _i : oi;                                   \
        _v = g ? ov : _v; _i = g ? oi : _i; } } } while(0)

// ---------------- prep: xx = 0.5 * sum_c x^2 -------------------------------
__global__ void prep_xx(const float* __restrict__ x) {
    int b = blockIdx.y;
    int n = blockIdx.x*256 + threadIdx.x;
    const float* xb = x + b*C*NPTS + n;
    float s = 0.f;
    #pragma unroll 8
    for (int c = 0; c < C; c++) { float v = xb[c*NPTS]; s = fmaf(v, v, s); }
    d_xx[b*NPTS + n] = 0.5f * s;
}

// --------- prep: stacked bf16 weights Ws[j][k] = Whi | Whi | Wlo -----------
__global__ void prep_wbf(const float* __restrict__ W) {
    int e = blockIdx.x*256 + threadIdx.x;       // e < 512*256
    int j = e >> 8, c = e & 255;
    float w;
    if (j < 256) w = W[j*C2 + c];
    else { int o = j - 256; w = W[o*C2 + 256 + c] - W[o*C2 + c]; }
    __nv_bfloat16 hi = __float2bfloat16(w);
    __nv_bfloat16 lo = __float2bfloat16(w - __bfloat162float(hi));
    uint16_t hb = __bfloat16_as_ushort(hi), lb = __bfloat16_as_ushort(lo);
    d_Ws[(size_t)j*768 + c]       = hb;
    d_Ws[(size_t)j*768 + 256 + c] = hb;
    d_Ws[(size_t)j*768 + 512 + c] = lb;
}

// ------- prep: bf16 hi/lo split + fp32 transpose, both to [b][n][.] --------
__global__ void __launch_bounds__(256) prep_split(const float* __restrict__ x) {
    __shared__ float tile[64][65];
    int b = blockIdx.z, c0 = blockIdx.y*64, n0 = blockIdx.x*64;
    int tid = threadIdx.x;
    #pragma unroll
    for (int i = 0; i < 16; i++) {
        int e = tid + 256*i;
        int cl = e >> 6, nl = e & 63;
        tile[cl][nl] = x[(b*C + c0 + cl)*NPTS + n0 + nl];
    }
    __syncthreads();
    int nl = tid >> 2, cq = (tid & 3) * 16;
    uint16_t* oh = d_xs + ((size_t)(b*NPTS + n0 + nl))*KHW + c0 + cq;
    uint16_t* ol = oh + 256;
    float*    ot = d_xt + ((size_t)(b*NPTS + n0 + nl))*C + c0 + cq;
    #pragma unroll
    for (int j = 0; j < 16; j += 2) {
        float v0 = tile[cq+j][nl],  v1 = tile[cq+j+1][nl];
        __nv_bfloat16 h0 = __float2bfloat16(v0), h1 = __float2bfloat16(v1);
        __nv_bfloat16 l0 = __float2bfloat16(v0 - __bfloat162float(h0));
        __nv_bfloat16 l1 = __float2bfloat16(v1 - __bfloat162float(h1));
        *(uint32_t*)(oh + j) = (uint32_t)__bfloat16_as_ushort(h0) | ((uint32_t)__bfloat16_as_ushort(h1) << 16);
        *(uint32_t*)(ol + j) = (uint32_t)__bfloat16_as_ushort(l0) | ((uint32_t)__bfloat16_as_ushort(l1) << 16);
        *(float2*)(ot + j) = make_float2(v0, v1);
    }
}

// ------------------- knn body (blocks 0..127 of megakernel) ----------------
// bf16 HMMA, K=256, 16 warps, warp tile 16x64 (R10-best shape).
#define SMA   0                      // 128*528 = 67584
#define SMB   67584                  // 2 * 67584
#define SMBUF 67584
#define SMXX  202752                 // 16384
#define SMTOT 219136
#define SMCV  SMB                    // merge buffers alias B buf0
#define SMCI  (SMB + 20480)

__device__ void knn_body(char* smem, uint32_t sb, int b, int n0) {
    int tid = threadIdx.x, lane = tid & 31, wid = tid >> 5;
    int ngrp = wid >> 1, mhalf = wid & 1;
    const uint16_t* xsb = d_xs + (size_t)b*NPTS*KHW;

    // group0: A (hi 256 hw) + xx + B chunk 0
    #pragma unroll
    for (int i = 0; i < 8; i++) {
        int c = tid + 512*i; int row = c >> 5, col = c & 31;
        cp16(sb + SMA + row*528 + col*16, xsb + (size_t)(n0+row)*KHW + col*8);
    }
    #pragma unroll
    for (int i = 0; i < 2; i++) {
        int c = tid + 512*i;
        cp16(sb + SMXX + c*16, d_xx + b*NPTS + c*4);
    }
    #pragma unroll
    for (int i = 0; i < 8; i++) {
        int c = tid + 512*i; int row = c >> 5, col = c & 31;
        cp16(sb + SMB + row*528 + col*16, xsb + (size_t)row*KHW + col*8);
    }
    CP_COMMIT();
    // group1: B chunk 1
    #pragma unroll
    for (int i = 0; i < 8; i++) {
        int c = tid + 512*i; int row = c >> 5, col = c & 31;
        cp16(sb + SMB + SMBUF + row*528 + col*16, xsb + (size_t)(128+row)*KHW + col*8);
    }
    CP_COMMIT();

    float tv[2][5]; int tix[2][5];
    #pragma unroll
    for (int L = 0; L < 2; L++)
        #pragma unroll
        for (int j = 0; j < 5; j++) { tv[L][j] = -CUDART_INF_F; tix[L][j] = 0; }
    const float* xx_s = (const float*)(smem + SMXX);

    int q = lane >> 3, l7 = lane & 7;
    uint32_t arow = (uint32_t)((ngrp*16 + (q & 1)*8 + l7)*528 + (q >> 1)*16);
    uint32_t brow = (uint32_t)((mhalf*64 + (q >> 1)*8 + l7)*528 + (q & 1)*16);

    for (int mt = 0; mt < 32; mt++) {
        CP_WAIT1();
        __syncthreads();
        float acc[8][4];
        #pragma unroll
        for (int t = 0; t < 8; t++)
            #pragma unroll
            for (int j = 0; j < 4; j++) acc[t][j] = 0.f;

        uint32_t ba = sb + SMA + arow;
        uint32_t bb = sb + SMB + (mt & 1)*SMBUF + brow;
        #pragma unroll
        for (int ks = 0; ks < 16; ks++) {
            uint32_t a0[4];
            ldsm4(a0[0], a0[1], a0[2], a0[3], ba + ks*32);
            #pragma unroll
            for (int p = 0; p < 4; p++) {
                uint32_t b0, b1, b2, b3;
                ldsm4(b0, b1, b2, b3, bb + p*8448 + ks*32);
                mma16816(acc[2*p],   a0, b0, b1);
                mma16816(acc[2*p+1], a0, b2, b3);
            }
        }
        // epilogue: rank value <n,m> - 0.5||m||^2, streaming top-5
        int m0 = mt * 128;
        #pragma unroll
        for (int t = 0; t < 8; t++) {
            int cb = m0 + mhalf*64 + t*8 + 2*(lane & 3);
            float xm0 = xx_s[cb], xm1 = xx_s[cb + 1];
            float v; int ii;
            v = acc[t][0] - xm0; ii = cb;     INS5(tv[0], tix[0]);
            v = acc[t][1] - xm1; ii = cb + 1; INS5(tv[0], tix[0]);
            v = acc[t][2] - xm0; ii = cb;     INS5(tv[1], tix[1]);
            v = acc[t][3] - xm1; ii = cb + 1; INS5(tv[1], tix[1]);
        }
        __syncthreads();   // all warps done reading buffer mt&1
        if (mt + 2 < 32) {
            int nm = mt + 2;
            #pragma unroll
            for (int i = 0; i < 8; i++) {
                int c = tid + 512*i; int row = c >> 5, col = c & 31;
                cp16(sb + SMB + (mt & 1)*SMBUF + row*528 + col*16,
                     xsb + (size_t)(nm*128 + row)*KHW + col*8);
            }
        }
        CP_COMMIT();       // possibly-empty group keeps depth constant
    }

    // merge: per row, 2 col-half warps x 4 lanes x 5 = 40 candidates -> top-12
    float* cv  = (float*)(smem + SMCV);
    int*   cix = (int*)  (smem + SMCI);
    int slot = (mhalf*4 + (lane & 3)) * 5;
    #pragma unroll
    for (int L = 0; L < 2; L++) {
        int r = ngrp*16 + L*8 + (lane >> 2);
        #pragma unroll
        for (int j = 0; j < 5; j++) {
            cv [r*40 + slot + j] = tv[L][j];
            cix[r*40 + slot + j] = tix[L][j];
        }
    }
    __syncthreads();
    if (tid < 128) {
        #pragma unroll
        for (int s = 0; s < NC; s++) {
            float best = -CUDART_INF_F; int bi = 0;
            for (int e = 0; e < 40; e++) {
                float v = cv[tid*40 + e];
                if (v > best) { best = v; bi = e; }
            }
            d_cand[(b*NPTS + n0 + tid)*NC + s] = cix[tid*40 + bi];
            cv[tid*40 + bi] = -CUDART_INF_F;
        }
    }
}

// ------------------- vu body (blocks 128..639 of megakernel) ---------------
// vu = Ws @ x via HMMA 3-term split (K=768), fp16 out. 512 threads: all load,
// warps 0-7 compute (same 8-warp tile map as the old 256-thread kernel).
#define VBUF 36864    // per buffer: As 128*144=18432 + Bs 18432

__device__ void vu_body(char* smem, uint32_t sb, int b, int m0, int j0) {
    int tid = threadIdx.x, lane = tid & 31, wid = tid >> 5;
    int ngrp = (wid >> 1) & 3, mhalf = wid & 1;

    int q = lane >> 3, l7 = lane & 7;
    uint32_t aoff = (uint32_t)((ngrp*32 + (q & 1)*8 + l7) * 144 + (q >> 1) * 16);
    uint32_t boff = (uint32_t)(18432 + (mhalf*64 + (q >> 1)*8 + l7) * 144 + (q & 1) * 16);

    #pragma unroll
    for (int pc = 0; pc < 2; pc++) {
        int koff = pc * 64;
        #pragma unroll
        for (int i = 0; i < 2; i++) {
            int c = tid + 512*i; int row = c >> 3, col = c & 7;
            cp16(sb + pc*VBUF + row*144 + col*16,
                 d_xs + (size_t)(b*NPTS + m0 + row)*KHW + koff + col*8);
            cp16(sb + pc*VBUF + 18432 + row*144 + col*16,
                 d_Ws + (size_t)(j0 + row)*768 + pc*64 + col*8);
        }
        CP_COMMIT();
    }

    float acc[2][8][4];
    #pragma unroll
    for (int ra = 0; ra < 2; ra++)
        #pragma unroll
        for (int t = 0; t < 8; t++)
            #pragma unroll
            for (int j = 0; j < 4; j++) acc[ra][t][j] = 0.f;

    for (int kc = 0; kc < 12; kc++) {
        CP_WAIT1();
        __syncthreads();
        if (wid < 8) {
            uint32_t ba = sb + (kc & 1)*VBUF;
            #pragma unroll
            for (int ks = 0; ks < 4; ks++) {
                uint32_t a0[4], a1[4];
                ldsm4(a0[0], a0[1], a0[2], a0[3], ba + aoff + ks*32);
                ldsm4(a1[0], a1[1], a1[2], a1[3], ba + aoff + 2304 + ks*32);
                #pragma unroll
                for (int p = 0; p < 4; p++) {
                    uint32_t b0, b1, b2, b3;
                    ldsm4(b0, b1, b2, b3, ba + boff + p*2304 + ks*32);
                    mma16816(acc[0][2*p],   a0, b0, b1);
                    mma16816(acc[0][2*p+1], a0, b2, b3);
                    mma16816(acc[1][2*p],   a1, b0, b1);
                    mma16816(acc[1][2*p+1], a1, b2, b3);
                }
            }
        }
        __syncthreads();
        if (kc + 2 < 12) {
            int nc2 = kc + 2;
            int koff = (nc2 < 8) ? nc2*64 : (nc2 - 8)*64;
            #pragma unroll
            for (int i = 0; i < 2; i++) {
                int c = tid + 512*i; int row = c >> 3, col = c & 7;
                cp16(sb + (kc & 1)*VBUF + row*144 + col*16,
                     d_xs + (size_t)(b*NPTS + m0 + row)*KHW + koff + col*8);
                cp16(sb + (kc & 1)*VBUF + 18432 + row*144 + col*16,
                     d_Ws + (size_t)(j0 + row)*768 + nc2*64 + col*8);
            }
        }
        CP_COMMIT();
    }

    if (wid < 8) {
        #pragma unroll
        for (int ra = 0; ra < 2; ra++) {
            int r  = m0 + ngrp*32 + ra*16 + (lane >> 2);
            #pragma unroll
            for (int t = 0; t < 8; t++) {
                int cb = j0 + mhalf*64 + t*8 + 2*(lane & 3);
                __half2 h0 = __floats2half2_rn(acc[ra][t][0], acc[ra][t][1]);
                __half2 h1 = __floats2half2_rn(acc[ra][t][2], acc[ra][t][3]);
                *(__half2*)&d_vu[(size_t)(b*NPTS + r)*C2 + cb]     = h0;
                *(__half2*)&d_vu[(size_t)(b*NPTS + r + 8)*C2 + cb] = h1;
            }
        }
    }
}

// ------------- megakernel: blocks 0..127 knn, 128..639 vu ------------------
__global__ void __launch_bounds__(512, 1) fused_mma() {
    extern __shared__ __align__(16) char smem[];
    uint32_t sb = smem_u32(smem);
    int bx = blockIdx.x;
    if (bx < 128) {
        knn_body(smem, sb, bx >> 5, (bx & 31) * 128);
    } else {
        int vb = bx - 128;                  // 0..511 = 4b x 32m x 4j
        int b  = vb >> 7;
        int rem = vb & 127;
        vu_body(smem, sb, b, (rem & 31) * 128, (rem >> 5) * 128);
    }
}

// -------- verify: exact fp32 re-rank of the 12 candidates, warp/point ------
// rank value = <q,m> - 0.5||m||^2 (final selection MUST be exact fp32)
__global__ void __launch_bounds__(128) verify_kernel() {
    int gw   = (blockIdx.x*128 + threadIdx.x) >> 5;
    int lane = threadIdx.x & 31;
    int b = gw >> 12;
    const float* xq = d_xt + (size_t)gw*C;
    float4 q0 = ((const float4*)xq)[lane];
    float4 q1 = ((const float4*)xq)[lane + 32];
    float pw[NC]; int cid[NC];
    #pragma unroll
    for (int k = 0; k < NC; k++) {
        int m = d_cand[gw*NC + k];
        cid[k] = m;
        const float* xc = d_xt + ((size_t)(b*NPTS + m))*C;
        float4 c0 = ((const float4*)xc)[lane];
        float4 c1 = ((const float4*)xc)[lane + 32];
        float s = 0.f;
        s = fmaf(q0.x, c0.x, s); s = fmaf(q0.y, c0.y, s);
        s = fmaf(q0.z, c0.z, s); s = fmaf(q0.w, c0.w, s);
        s = fmaf(q1.x, c1.x, s); s = fmaf(q1.y, c1.y, s);
        s = fmaf(q1.z, c1.z, s); s = fmaf(q1.w, c1.w, s);
        #pragma unroll
        for (int o = 16; o > 0; o >>= 1) s += __shfl_xor_sync(0xFFFFFFFFu, s, o);
        pw[k] = s - d_xx[b*NPTS + m];
    }
    if (lane == 0) {
        #pragma unroll
        for (int s5 = 0; s5 < KNN; s5++) {
            float best = -CUDART_INF_F; int bi = 0;
            #pragma unroll
            for (int e = 0; e < NC; e++) if (pw[e] > best) { best = pw[e]; bi = e; }
            d_idx[gw*KNN + s5] = cid[bi];
            pw[bi] = -CUDART_INF_F;
        }
    }
}

// ---------------- BN stats (fp16 vu) ---------------------------------------
__global__ void __launch_bounds__(256) stats_kernel() {
    int b  = blockIdx.y;
    int n0 = blockIdx.x * 64;
    int o  = threadIdx.x;
    float s = 0.f, s2 = 0.f;
    for (int nl = 0; nl < 64; nl++) {
        int n = n0 + nl;
        const __half* vun = d_vu + (size_t)(b*NPTS + n)*C2;
        float u = __half2float(vun[256 + o]);
        const int* ip = d_idx + (b*NPTS + n)*KNN;
        #pragma unroll
        for (int k = 0; k < KNN; k++) {
            int m = ip[k];
            float y = __half2float(d_vu[(size_t)(b*NPTS + m)*C2 + o]) + u;
            s += y;
            s2 = fmaf(y, y, s2);
        }
    }
    int pb = blockIdx.y*64 + blockIdx.x;
    d_psum [pb*C + o] = s;
    d_psum2[pb*C + o] = s2;
}

__global__ void bn_finalize(const float* __restrict__ gamma, const float* __restrict__ beta) {
    int o = threadIdx.x;
    float s = 0.f, s2 = 0.f;
    for (int pb = 0; pb < 256; pb++) { s += d_psum[pb*C + o]; s2 += d_psum2[pb*C + o]; }
    float cnt  = (float)(B*NPTS*KNN);
    float mean = s / cnt;
    float var  = s2 / cnt - mean*mean;
    float sc   = gamma[o] * rsqrtf(var + 1e-5f);
    d_scale[o] = sc;
    d_shift[o] = beta[o] - mean*sc;
}

// ---------------- final (fp16 vu) ------------------------------------------
__global__ void __launch_bounds__(256) final_kernel(const float* __restrict__ x,
                                                    float* __restrict__ out) {
    __shared__ float res[256][33];
    int b = blockIdx.y, n0 = blockIdx.x*32;
    int o = threadIdx.x;
    float sc = d_scale[o], sh = d_shift[o];
    for (int nl = 0; nl < 32; nl++) {
        int n = n0 + nl;
        const __half* vun = d_vu + (size_t)(b*NPTS + n)*C2;
        float u  = __half2float(vun[256 + o]);
        float cc = fmaf(u, sc, sh);
        const int* ip = d_idx + (b*NPTS + n)*KNN;
        float mx = -CUDART_INF_F;
        #pragma unroll
        for (int k = 0; k < KNN; k++) {
            float v = __half2float(d_vu[(size_t)(b*NPTS + ip[k])*C2 + o]);
            mx = fmaxf(mx, fmaf(v, sc, cc));
        }
        res[o][nl] = fmaxf(mx, 0.f);
    }
    __syncthreads();
    int lane = threadIdx.x & 31, og = threadIdx.x >> 5;
    #pragma unroll 4
    for (int p = 0; p < 32; p++) {
        int oo = p*8 + og;
        int gi = (b*C + oo)*NPTS + n0 + lane;
        out[gi] = res[oo][lane] + x[gi];
    }
}

// ---------------- launch (single stream, graph-capture safe) ---------------
extern "C" void kernel_launch(void* const* d_in, const int* in_sizes, int n_in,
                              void* d_out, int out_size) {
    const float* x     = (const float*)d_in[0];
    const float* W     = (const float*)d_in[1];
    const float* gamma = (const float*)d_in[2];
    const float* beta  = (const float*)d_in[3];
    float* out = (float*)d_out;

    cudaFuncSetAttribute(fused_mma, cudaFuncAttributeMaxDynamicSharedMemorySize, SMTOT);

    prep_xx      <<<dim3(NPTS/256, B), 256>>>(x);
    prep_wbf     <<<dim3(C2*C/256), 256>>>(W);
    prep_split   <<<dim3(NPTS/64, C/64, B), 256>>>(x);
    fused_mma    <<<dim3(128 + 512), 512, SMTOT>>>();
    verify_kernel<<<dim3(B*NPTS/4), 128>>>();
    stats_kernel <<<dim3(NPTS/64, B), 256>>>();
    bn_finalize  <<<1, 256>>>(gamma, beta);
    final_kernel <<<dim3(NPTS/32, B), 256>>>(x, out);
}